// round 17
// baseline (speedup 1.0000x reference)
#include <cuda_runtime.h>
#include <cuda.h>
#include <cuda_fp16.h>
#include <cstdint>

// Problem shape (fixed by dataset)
#define M_TOKENS 16384
#define K_DIM    2048
#define N_DIM    2048
#define EPS      1e-7f

// GEMM tiling: 128x128 CTA tile, K-chunk = 64 fp16 = 128 B per stage
#define BM 128
#define BN 128
#define NSTAGE 3
#define NKT 32
#define STAGE_B 32768                 // A 16KB + B 16KB, SW128-swizzled, pitch 128
#define SMEM_BARS (NSTAGE * STAGE_B)  // 98304
#define FULL_BAR(s)  (SMEM_BARS + (s) * 8)
#define EMPTY_BAR(s) (SMEM_BARS + 32 + (s) * 8)
#define SMEM_TOTAL (SMEM_BARS + 64)

// Persistent grid
#define GRIDSZ 296                    // 2 CTAs x 148 SMs, one wave
#define TILES_N (N_DIM / BN)          // 16
#define TILES_TOTAL ((M_TOKENS / BM) * TILES_N)  // 2048

// Prep-kernel grid split
#define PACK_BLOCKS 4096              // N*K/4/256
#define QUANT_BLOCKS M_TOKENS

// Scratch (device globals)
__device__ __align__(1024) __half g_qh[(size_t)M_TOKENS * K_DIM];  // fp16 activations
__device__ __align__(1024) __half g_wh[(size_t)N_DIM * K_DIM];     // fp16 weights
__device__ float g_scales[M_TOKENS];

// ---------------------------------------------------------------------------
// Kernel 0+1 merged: weight pack + per-token quantization (both HBM-roofline).
// ---------------------------------------------------------------------------
__global__ __launch_bounds__(256) void prep_kernel(const float* __restrict__ x,
                                                   const int* __restrict__ w32) {
    if (blockIdx.x < PACK_BLOCKS) {
        const int idx = blockIdx.x * blockDim.x + threadIdx.x;
        int4 v = reinterpret_cast<const int4*>(w32)[idx];
        __half2 h0 = __halves2half2(__int2half_rn(v.x), __int2half_rn(v.y));
        __half2 h1 = __halves2half2(__int2half_rn(v.z), __int2half_rn(v.w));
        uint2 hp = make_uint2(*(uint32_t*)&h0, *(uint32_t*)&h1);
        reinterpret_cast<uint2*>(g_wh)[idx] = hp;
        return;
    }

    const int token = blockIdx.x - PACK_BLOCKS;
    const int tid = threadIdx.x;
    const int lane = tid & 31;
    const int warp = tid >> 5;

    const float4* xr = reinterpret_cast<const float4*>(x + (size_t)token * K_DIM);
    float4 v0 = xr[tid * 2 + 0];
    float4 v1 = xr[tid * 2 + 1];

    float m = fabsf(v0.x);
    m = fmaxf(m, fabsf(v0.y)); m = fmaxf(m, fabsf(v0.z)); m = fmaxf(m, fabsf(v0.w));
    m = fmaxf(m, fabsf(v1.x)); m = fmaxf(m, fabsf(v1.y));
    m = fmaxf(m, fabsf(v1.z)); m = fmaxf(m, fabsf(v1.w));

    #pragma unroll
    for (int off = 16; off > 0; off >>= 1)
        m = fmaxf(m, __shfl_xor_sync(0xFFFFFFFFu, m, off));

    __shared__ float wmax[8];
    if (lane == 0) wmax[warp] = m;
    __syncthreads();
    if (warp == 0) {
        float t = (lane < 8) ? wmax[lane] : 0.0f;
        #pragma unroll
        for (int off = 4; off > 0; off >>= 1)
            t = fmaxf(t, __shfl_xor_sync(0xFFFFFFFFu, t, off));
        if (lane == 0) wmax[0] = t;
    }
    __syncthreads();
    const float absmax = wmax[0];
    const float scale = fmaxf(absmax, EPS) / 127.0f;

    if (tid == 0) g_scales[token] = scale;

    const float inv = 1.0f / scale;
    float vals[8] = {v0.x, v0.y, v0.z, v0.w, v1.x, v1.y, v1.z, v1.w};
    int qv[8];
    #pragma unroll
    for (int i = 0; i < 8; i++) {
        float q = rintf(vals[i] * inv);
        q = fminf(fmaxf(q, -128.0f), 127.0f);
        qv[i] = (int)q;
    }
    uint4 hq;
    __half2 h;
    h = __halves2half2(__int2half_rn(qv[0]), __int2half_rn(qv[1])); hq.x = *(uint32_t*)&h;
    h = __halves2half2(__int2half_rn(qv[2]), __int2half_rn(qv[3])); hq.y = *(uint32_t*)&h;
    h = __halves2half2(__int2half_rn(qv[4]), __int2half_rn(qv[5])); hq.z = *(uint32_t*)&h;
    h = __halves2half2(__int2half_rn(qv[6]), __int2half_rn(qv[7])); hq.w = *(uint32_t*)&h;
    *reinterpret_cast<uint4*>(g_qh + (size_t)token * K_DIM + tid * 8) = hq;
}

// ---------------------------------------------------------------------------
// PTX helpers (TMA + mbarrier)
// ---------------------------------------------------------------------------
__device__ __forceinline__ void mbar_init(uint32_t a, uint32_t cnt) {
    asm volatile("mbarrier.init.shared.b64 [%0], %1;" :: "r"(a), "r"(cnt) : "memory");
}
__device__ __forceinline__ void mbar_arrive(uint32_t a) {
    asm volatile("mbarrier.arrive.shared.b64 _, [%0];" :: "r"(a) : "memory");
}
__device__ __forceinline__ void mbar_expect_tx(uint32_t a, uint32_t bytes) {
    asm volatile("mbarrier.arrive.expect_tx.shared.b64 _, [%0], %1;" :: "r"(a), "r"(bytes) : "memory");
}
__device__ __forceinline__ void mbar_wait(uint32_t a, uint32_t parity) {
    asm volatile(
        "{\n\t.reg .pred P;\n"
        "W1_%=:\n\t"
        "mbarrier.try_wait.parity.acquire.cta.shared::cta.b64 P, [%0], %1, 0x989680;\n\t"
        "@P bra.uni W2_%=;\n\t"
        "bra.uni W1_%=;\n"
        "W2_%=:\n\t}"
        :: "r"(a), "r"(parity) : "memory");
}
__device__ __forceinline__ void tma3d(uint32_t smem, const CUtensorMap* map, int x, int y, uint32_t mbar) {
    asm volatile(
        "cp.async.bulk.tensor.3d.shared::cta.global.tile.mbarrier::complete_tx::bytes "
        "[%0], [%1, {%2, %3, %4}], [%5];"
        :: "r"(smem), "l"(map), "r"(x), "r"(y), "r"(0), "r"(mbar) : "memory");
}
__device__ __forceinline__ void ldsm4(uint32_t& r0, uint32_t& r1, uint32_t& r2, uint32_t& r3,
                                      uint32_t addr) {
    asm volatile("ldmatrix.sync.aligned.m8n8.x4.shared.b16 {%0,%1,%2,%3}, [%4];"
                 : "=r"(r0), "=r"(r1), "=r"(r2), "=r"(r3) : "r"(addr));
}

// ---------------------------------------------------------------------------
// Kernel 2: PERSISTENT fp16 HMMA GEMM. 296 CTAs (2/SM, one wave), each
// processes ~7 tiles of 128x128. The TMA producer and the stage ring run
// continuously across tiles (global chunk stream): during tile t's epilogue
// the ring is already filling with tile t+1's chunks. Full/empty mbarrier
// protocol is identical to the validated R14/R15 kernel.
// ---------------------------------------------------------------------------
__global__ __launch_bounds__(256, 2) void gemm_f16_kernel(
    const __grid_constant__ CUtensorMap tma_a,
    const __grid_constant__ CUtensorMap tma_b,
    const float* __restrict__ w_scale,
    const float* __restrict__ bias,
    float* __restrict__ out)
{
    extern __shared__ char smem[];
    const uint32_t sb = (uint32_t)__cvta_generic_to_shared(smem);

    const int tid = threadIdx.x;
    const int lane = tid & 31;
    const int warp = tid >> 5;
    const int warpM = warp >> 2;   // 0..1 (64 rows)
    const int warpN = warp & 3;    // 0..3 (32 cols)
    const int g = lane >> 2;
    const int tg = lane & 3;

    const int bid = blockIdx.x;
    const int ntiles = (TILES_TOTAL - bid + GRIDSZ - 1) / GRIDSZ;
    const int totchunks = ntiles * NKT;

    if (tid == 0) {
        #pragma unroll
        for (int s = 0; s < NSTAGE; s++) {
            mbar_init(sb + FULL_BAR(s), 1);
            mbar_init(sb + EMPTY_BAR(s), 8);   // one arrive per warp
        }
    }
    __syncthreads();

    // Prologue: fill all NSTAGE stages with global chunks 0..NSTAGE-1
    // (all belong to this CTA's first tile since NKT >= NSTAGE).
    if (tid == 0) {
        const int t0 = bid;
        const int pm0 = (t0 / TILES_N) * BM;
        const int pn0 = (t0 % TILES_N) * BN;
        #pragma unroll
        for (int s = 0; s < NSTAGE; s++) {
            mbar_expect_tx(sb + FULL_BAR(s), STAGE_B);
            tma3d(sb + s * STAGE_B,         &tma_a, s * 128, pm0, sb + FULL_BAR(s));
            tma3d(sb + s * STAGE_B + 16384, &tma_b, s * 128, pn0, sb + FULL_BAR(s));
        }
    }

    // ldmatrix lane rows (validated layout) + SW128 per-lane XOR masks.
    const int aRow = warpM * 64 + (lane & 7) + ((lane >> 3) & 1) * 8;   // + mi*16
    const int aKof = (lane >> 4) * 16;
    const int bRow = warpN * 32 + (lane >> 4) * 8 + (lane & 7);         // + j2*16
    const int bKof = ((lane >> 3) & 1) * 16;
    const int aXor = (aRow & 7) * 16;
    const int bXor = (bRow & 7) * 16;

    int cstage = 0, cph = 0;   // consumer cursor (full bars), continuous
    int pph = 0;               // producer empty-wait parity, continuous
    int ci = 0;                // global consumed-chunk counter

    #pragma unroll 1
    for (int lt = 0; lt < ntiles; lt++) {
        const int t = bid + lt * GRIDSZ;
        const int m0 = (t / TILES_N) * BM;
        const int n0 = (t % TILES_N) * BN;

        float acc[4][4][4];
        #pragma unroll
        for (int mi = 0; mi < 4; mi++)
            #pragma unroll
            for (int ni = 0; ni < 4; ni++)
                #pragma unroll
                for (int r = 0; r < 4; r++) acc[mi][ni][r] = 0.0f;

        #pragma unroll 1
        for (int kt = 0; kt < NKT; kt++) {
            mbar_wait(sb + FULL_BAR(cstage), cph);
            const uint32_t aBase = sb + cstage * STAGE_B;
            const uint32_t bBase = aBase + 16384;

            #pragma unroll
            for (int ks = 0; ks < 4; ks++) {
                const int k0 = ks * 32;
                uint32_t afr[4][4];
                #pragma unroll
                for (int mi = 0; mi < 4; mi++) {
                    const int row = aRow + mi * 16;
                    ldsm4(afr[mi][0], afr[mi][1], afr[mi][2], afr[mi][3],
                          aBase + row * 128 + ((k0 + aKof) ^ aXor));
                }
                uint32_t bfr[4][2];
                #pragma unroll
                for (int j2 = 0; j2 < 2; j2++) {
                    const int row = bRow + j2 * 16;
                    uint32_t b0, b1, b2, b3;
                    ldsm4(b0, b1, b2, b3, bBase + row * 128 + ((k0 + bKof) ^ bXor));
                    bfr[2 * j2][0] = b0; bfr[2 * j2][1] = b1;
                    bfr[2 * j2 + 1][0] = b2; bfr[2 * j2 + 1][1] = b3;
                }
                #pragma unroll
                for (int mi = 0; mi < 4; mi++)
                    #pragma unroll
                    for (int ni = 0; ni < 4; ni++) {
                        asm volatile(
                            "mma.sync.aligned.m16n8k16.row.col.f32.f16.f16.f32 "
                            "{%0,%1,%2,%3}, {%4,%5,%6,%7}, {%8,%9}, {%0,%1,%2,%3};\n"
                            : "+f"(acc[mi][ni][0]), "+f"(acc[mi][ni][1]),
                              "+f"(acc[mi][ni][2]), "+f"(acc[mi][ni][3])
                            : "r"(afr[mi][0]), "r"(afr[mi][1]), "r"(afr[mi][2]), "r"(afr[mi][3]),
                              "r"(bfr[ni][0]), "r"(bfr[ni][1]));
                    }
            }

            // Warp-elected empty arrive (mma.sync convergence orders all lanes'
            // smem reads before lane 0's arrive).
            if (lane == 0) mbar_arrive(sb + EMPTY_BAR(cstage));

            // Producer: refill just-consumed stage with global chunk ci+NSTAGE
            // (may belong to the NEXT tile -> cross-tile prefetch).
            const int pf = ci + NSTAGE;
            if (tid == 0 && pf < totchunks) {
                const int plt = pf >> 5;                      // local tile index
                const int pt = bid + plt * GRIDSZ;            // global tile
                const int pm0 = (pt / TILES_N) * BM;
                const int pn0 = (pt % TILES_N) * BN;
                const int pkt = pf & 31;
                mbar_wait(sb + EMPTY_BAR(cstage), pph);
                mbar_expect_tx(sb + FULL_BAR(cstage), STAGE_B);
                tma3d(sb + cstage * STAGE_B,         &tma_a, pkt * 128, pm0, sb + FULL_BAR(cstage));
                tma3d(sb + cstage * STAGE_B + 16384, &tma_b, pkt * 128, pn0, sb + FULL_BAR(cstage));
            }

            ci++;
            if (++cstage == NSTAGE) { cstage = 0; cph ^= 1; pph ^= 1; }
        }

        // Epilogue for tile t (runs while the ring prefetches tile t+1).
        #pragma unroll
        for (int mi = 0; mi < 4; mi++) {
            const int r0 = m0 + warpM * 64 + mi * 16 + g;
            const float s0 = g_scales[r0];
            const float s1 = g_scales[r0 + 8];
            #pragma unroll
            for (int ni = 0; ni < 4; ni++) {
                const int c = n0 + warpN * 32 + ni * 8 + tg * 2;
                const float w0 = w_scale[c], w1 = w_scale[c + 1];
                const float b0 = bias[c],    b1 = bias[c + 1];
                float2 o0, o1;
                o0.x = __half2float(__float2half_rn(acc[mi][ni][0] * s0 * w0 + b0));
                o0.y = __half2float(__float2half_rn(acc[mi][ni][1] * s0 * w1 + b1));
                o1.x = __half2float(__float2half_rn(acc[mi][ni][2] * s1 * w0 + b0));
                o1.y = __half2float(__float2half_rn(acc[mi][ni][3] * s1 * w1 + b1));
                *reinterpret_cast<float2*>(out + (size_t)r0 * N_DIM + c) = o0;
                *reinterpret_cast<float2*>(out + (size_t)(r0 + 8) * N_DIM + c) = o1;
            }
        }
    }
}

// ---------------------------------------------------------------------------
// Host launcher
// ---------------------------------------------------------------------------
typedef CUresult (*PFN_encodeTiled)(
    CUtensorMap*, CUtensorMapDataType, cuuint32_t, void*,
    const cuuint64_t*, const cuuint64_t*, const cuuint32_t*, const cuuint32_t*,
    CUtensorMapInterleave, CUtensorMapSwizzle, CUtensorMapL2promotion,
    CUtensorMapFloatOOBfill);

extern "C" void kernel_launch(void* const* d_in, const int* in_sizes, int n_in,
                              void* d_out, int out_size) {
    const float* x       = (const float*)d_in[0];
    const int*   weight  = (const int*)d_in[1];   // int8 marshalled as int32
    const float* w_scale = (const float*)d_in[2];
    const float* bias    = (const float*)d_in[3];
    float* out = (float*)d_out;

    prep_kernel<<<PACK_BLOCKS + QUANT_BLOCKS, 256>>>(x, weight);

    void* qptr = nullptr;
    void* wptr = nullptr;
    cudaGetSymbolAddress(&qptr, g_qh);
    cudaGetSymbolAddress(&wptr, g_wh);

    PFN_encodeTiled enc = nullptr;
    cudaDriverEntryPointQueryResult qres;
    cudaGetDriverEntryPointByVersion("cuTensorMapEncodeTiled", (void**)&enc, 12000,
                                     cudaEnableDefault, &qres);

    // Byte-typed views of the fp16 matrices: dims {K bytes, rows, 1}, SW128.
    CUtensorMap ta, tb;
    cuuint64_t dimsA[3] = {K_DIM * 2, M_TOKENS, 1};
    cuuint64_t strA[2]  = {K_DIM * 2, (cuuint64_t)(K_DIM * 2) * M_TOKENS};
    cuuint64_t dimsB[3] = {K_DIM * 2, N_DIM, 1};
    cuuint64_t strB[2]  = {K_DIM * 2, (cuuint64_t)(K_DIM * 2) * N_DIM};
    cuuint32_t box[3]   = {128, 128, 1};
    cuuint32_t es[3]    = {1, 1, 1};

    enc(&ta, CU_TENSOR_MAP_DATA_TYPE_UINT8, 3, qptr, dimsA, strA, box, es,
        CU_TENSOR_MAP_INTERLEAVE_NONE, CU_TENSOR_MAP_SWIZZLE_128B,
        CU_TENSOR_MAP_L2_PROMOTION_L2_128B, CU_TENSOR_MAP_FLOAT_OOB_FILL_NONE);
    enc(&tb, CU_TENSOR_MAP_DATA_TYPE_UINT8, 3, wptr, dimsB, strB, box, es,
        CU_TENSOR_MAP_INTERLEAVE_NONE, CU_TENSOR_MAP_SWIZZLE_128B,
        CU_TENSOR_MAP_L2_PROMOTION_L2_128B, CU_TENSOR_MAP_FLOAT_OOB_FILL_NONE);

    cudaFuncSetAttribute(gemm_f16_kernel, cudaFuncAttributeMaxDynamicSharedMemorySize, SMEM_TOTAL);
    gemm_f16_kernel<<<GRIDSZ, 256, SMEM_TOTAL>>>(ta, tb, w_scale, bias, out);
}